// round 13
// baseline (speedup 1.0000x reference)
#include <cuda_runtime.h>

// x [4194304, 8] fp32. Keep row iff expert 0 is in the row's top-2
// (top_k ties break low-index -> expert 0), else zero it.
// Predicate: count(x[j] > x[0], j=1..7) <= 1.
//
// R3 body (best measured: 37.1us ncu, DRAM 72.5%) wrapped in a minimal
// persistent grid-stride loop:
//  - 1 row per iteration -> MLP_p1 stays 2 (measured optimum; 4 and 8
//    both regressed via cross-CTA L1tex-queue spread)
//  - ~20 regs -> occupancy stays 8 CTAs/SM
//  - single wave (1216 CTAs) -> no wave-transition overhead (the one
//    un-isolated term in R3's 16384-CTA / 13.5-wave launch)
//  - plain LDG/STG: ~20% of traffic hits L2 (126MB L2 vs 256MB stream);
//    .cs evict-first measurably hurts (R10) and is deliberately absent.

__global__ void __launch_bounds__(256)
routing_e0_kernel(const float4* __restrict__ in,
                  float4* __restrict__ out,
                  int nrows)
{
    const int stride = gridDim.x * blockDim.x;
    for (int row = blockIdx.x * blockDim.x + threadIdx.x;
         row < nrows;
         row += stride)
    {
        float4 a = in[2 * row];       // x[0..3]
        float4 b = in[2 * row + 1];   // x[4..7]

        float x0 = a.x;
        int cnt = (a.y > x0) + (a.z > x0) + (a.w > x0)
                + (b.x > x0) + (b.y > x0) + (b.z > x0) + (b.w > x0);

        float keep = (cnt <= 1) ? 1.0f : 0.0f;

        float4 ra, rb;
        ra.x = a.x * keep;  ra.y = a.y * keep;
        ra.z = a.z * keep;  ra.w = a.w * keep;
        rb.x = b.x * keep;  rb.y = b.y * keep;
        rb.z = b.z * keep;  rb.w = b.w * keep;

        out[2 * row]     = ra;
        out[2 * row + 1] = rb;
    }
}

extern "C" void kernel_launch(void* const* d_in, const int* in_sizes, int n_in,
                              void* d_out, int out_size)
{
    const float4* in  = (const float4*)d_in[0];
    float4*       out = (float4*)d_out;

    int n_elems = in_sizes[0];     // SEQ_LEN * 8 floats
    int nrows = n_elems / 8;       // 4194304

    const int threads = 256;
    const int blocks  = 152 * 8;   // single wave: 152 SMs x 8 CTAs (occ-limited)
    routing_e0_kernel<<<blocks, threads>>>(in, out, nrows);
}

// round 14
// speedup vs baseline: 1.1445x; 1.1445x over previous
#include <cuda_runtime.h>

// x [4194304, 8] fp32. Keep row iff expert 0 is in the row's top-2
// (top_k ties break low-index -> expert 0), else zero it.
// Predicate: count(x[j] > x[0], j=1..7) <= 1.
//
// MLP_p1 = 1 variant: ONE float4 (half a row) per thread, flat launch.
// Measured trend (DRAM%): MLP_p1 8 -> 58.7, 4 -> 69.1, 2 -> 72.5; this
// tests the endpoint. Lane pairs (even, odd) share a row: x0 comes from
// the even lane via one shfl, the ">x0" counts merge via one shfl.bfly.
// Issue was 15.9% at MLP_p1=2 -> the 2 shfls are free. Flat launch only:
// persistent grids measurably regress (R10, R13).

__global__ void __launch_bounds__(256)
routing_e0_kernel(const float4* __restrict__ in,
                  float4* __restrict__ out,
                  int n4)
{
    int i = blockIdx.x * blockDim.x + threadIdx.x;
    if (i >= n4) return;

    float4 v = in[i];   // single LDG.128 in flight per thread (MLP_p1 = 1)

    int lane = threadIdx.x & 31;
    // Partner exchange: odd lane receives even lane's v.x (= row's x[0]).
    float px = __shfl_xor_sync(0xFFFFFFFFu, v.x, 1, 32);
    float x0 = (lane & 1) ? px : v.x;

    // Even lane's v.x IS x0 (x0 > x0 false), so an unconditional 4-compare
    // count is exact for both lanes -> no divergence.
    int cnt = (v.x > x0) + (v.y > x0) + (v.z > x0) + (v.w > x0);
    cnt += __shfl_xor_sync(0xFFFFFFFFu, cnt, 1, 32);

    float keep = (cnt <= 1) ? 1.0f : 0.0f;
    float4 r;
    r.x = v.x * keep;
    r.y = v.y * keep;
    r.z = v.z * keep;
    r.w = v.w * keep;
    out[i] = r;
}

extern "C" void kernel_launch(void* const* d_in, const int* in_sizes, int n_in,
                              void* d_out, int out_size)
{
    const float4* in  = (const float4*)d_in[0];
    float4*       out = (float4*)d_out;

    int n_elems = in_sizes[0];     // SEQ_LEN * 8 floats
    int n4 = n_elems / 4;          // float4 count (2 per row)

    const int threads = 256;
    int blocks = (n4 + threads - 1) / threads;   // 32768 for full shape
    routing_e0_kernel<<<blocks, threads>>>(in, out, n4);
}